// round 14
// baseline (speedup 1.0000x reference)
#include <cuda_runtime.h>
#include <math.h>
#include <stdint.h>

#define HID 512
#define TI_A 32
#define KV   10   // class size (N=K=10 problem family; S = N*K+1)

typedef unsigned long long ull;

__device__ __forceinline__ ull fma2(ull a, ull b, ull c) {
    ull d;
    asm("fma.rn.f32x2 %0, %1, %2, %3;" : "=l"(d) : "l"(a), "l"(b), "l"(c));
    return d;
}
__device__ __forceinline__ ull pack2(float lo, float hi) {
    ull d;
    asm("mov.b64 %0, {%1, %2};" : "=l"(d) : "f"(lo), "f"(hi));
    return d;
}
__device__ __forceinline__ float2 unpack2(ull a) {
    float lo, hi;
    asm("mov.b64 {%0, %1}, %2;" : "=f"(lo), "=f"(hi) : "l"(a));
    return make_float2(lo, hi);
}

// Fallback scratch for attn if d_out doesn't include the attn tensor.
__device__ float g_attn_scratch[64 * 128 * 128];

// ---------------------------------------------------------------------------
// Kernel A v6: scores = Q K^T / sqrt(H), softmax, write attn.
// Block: (batch b, 32-row tile) -> grid (64, 4) = 256 blocks (~2/SM).
// 64 threads = 2 warps; warp ty owns 16 i-rows (iy16..+15), all 128 j.
// Thread micro-tile: 16 i x 4 j, j = {2tx, 2tx+1, 2tx+64, 2tx+65}.
// Crossbar per warp-h2: Q 8 bcast + K 8 phases = 16 << fma 128 cyc ->
// FMA-BOUND (first A geometry where LDS is not the limiter).
// h in 16 chunks of 32 floats, double-buffered smem, 1 sync per chunk.
// ---------------------------------------------------------------------------
__global__ __launch_bounds__(64) void qk_softmax_kernel(
    const float* __restrict__ q, const float* __restrict__ k,
    float* __restrict__ attn, int S)
{
    __shared__ ull Qs2[2][16][34];    // [buf][h2][i]
    __shared__ ull Ks2[2][16][130];   // [buf][h2][j]

    const int b   = blockIdx.x;
    const int i0  = blockIdx.y * TI_A;
    const int tid = threadIdx.x;      // 0..63
    const int tx  = tid & 31;
    const int ty  = tid >> 5;         // 0..1
    const int iy16 = ty * 16;
    const int h2l  = tid & 15;        // h-pair lane for loads (0..15)
    const int rsel = tid >> 4;        // row selector for loads (0..3)

    const float* qb = q + (size_t)b * S * HID;
    const float* kb = k + (size_t)b * S * HID;

    ull acc2[16][4];
#pragma unroll
    for (int a = 0; a < 16; ++a)
#pragma unroll
        for (int c = 0; c < 4; ++c) acc2[a][c] = 0ull;

    auto load_chunk = [&](int c, int buf) {
        int h0 = c * 32;
        // Q: 32 rows x 16 pairs (each thread 8 rows)
#pragma unroll
        for (int r = 0; r < 8; ++r) {
            int il = rsel + 4 * r;
            int i  = i0 + il;
            float2 val = (i < S) ? *(const float2*)(qb + (size_t)i * HID + h0 + h2l * 2)
                                 : make_float2(0.f, 0.f);
            *(float2*)&Qs2[buf][h2l][il] = val;
        }
        // K: 128 rows x 16 pairs (each thread 32 rows)
#pragma unroll
        for (int r = 0; r < 32; ++r) {
            int j = rsel + 4 * r;
            float2 val = (j < S) ? *(const float2*)(kb + (size_t)j * HID + h0 + h2l * 2)
                                 : make_float2(0.f, 0.f);
            *(float2*)&Ks2[buf][h2l][j] = val;
        }
    };

    load_chunk(0, 0);
    __syncthreads();

#pragma unroll 1
    for (int c = 0; c < 16; ++c) {
        int cur = c & 1;
        if (c + 1 < 16) load_chunk(c + 1, cur ^ 1);   // overlap with compute

#pragma unroll
        for (int h2 = 0; h2 < 16; ++h2) {
            ulonglong2 ka = *(const ulonglong2*)&Ks2[cur][h2][2 * tx];
            ulonglong2 kc = *(const ulonglong2*)&Ks2[cur][h2][2 * tx + 64];
#pragma unroll
            for (int g = 0; g < 4; ++g) {
                ulonglong2 qa = *(const ulonglong2*)&Qs2[cur][h2][iy16 + 4 * g];
                ulonglong2 qc = *(const ulonglong2*)&Qs2[cur][h2][iy16 + 4 * g + 2];
                int r = 4 * g;
                acc2[r+0][0] = fma2(qa.x, ka.x, acc2[r+0][0]);
                acc2[r+0][1] = fma2(qa.x, ka.y, acc2[r+0][1]);
                acc2[r+0][2] = fma2(qa.x, kc.x, acc2[r+0][2]);
                acc2[r+0][3] = fma2(qa.x, kc.y, acc2[r+0][3]);
                acc2[r+1][0] = fma2(qa.y, ka.x, acc2[r+1][0]);
                acc2[r+1][1] = fma2(qa.y, ka.y, acc2[r+1][1]);
                acc2[r+1][2] = fma2(qa.y, kc.x, acc2[r+1][2]);
                acc2[r+1][3] = fma2(qa.y, kc.y, acc2[r+1][3]);
                acc2[r+2][0] = fma2(qc.x, ka.x, acc2[r+2][0]);
                acc2[r+2][1] = fma2(qc.x, ka.y, acc2[r+2][1]);
                acc2[r+2][2] = fma2(qc.x, kc.x, acc2[r+2][2]);
                acc2[r+2][3] = fma2(qc.x, kc.y, acc2[r+2][3]);
                acc2[r+3][0] = fma2(qc.y, ka.x, acc2[r+3][0]);
                acc2[r+3][1] = fma2(qc.y, ka.y, acc2[r+3][1]);
                acc2[r+3][2] = fma2(qc.y, kc.x, acc2[r+3][2]);
                acc2[r+3][3] = fma2(qc.y, kc.y, acc2[r+3][3]);
            }
        }
        __syncthreads();
    }

    const float inv_t = 0.04419417382415922f;  // 1/sqrt(512)

    const int c0 = 2 * tx;
    const int c2 = 2 * tx + 64;
    const bool v0 = (c0    ) < S;
    const bool v1 = (c0 + 1) < S;
    const bool v2 = (c2    ) < S;
    const bool v3 = (c2 + 1) < S;

#pragma unroll 1
    for (int si = 0; si < 16; ++si) {
        int i = i0 + iy16 + si;
        float2 a0 = unpack2(acc2[si][0]);
        float2 a1 = unpack2(acc2[si][1]);
        float2 a2 = unpack2(acc2[si][2]);
        float2 a3 = unpack2(acc2[si][3]);
        float s0 = v0 ? (a0.x + a0.y) * inv_t : -INFINITY;
        float s1 = v1 ? (a1.x + a1.y) * inv_t : -INFINITY;
        float s2 = v2 ? (a2.x + a2.y) * inv_t : -INFINITY;
        float s3 = v3 ? (a3.x + a3.y) * inv_t : -INFINITY;

        float m = fmaxf(fmaxf(s0, s1), fmaxf(s2, s3));
#pragma unroll
        for (int o = 16; o > 0; o >>= 1)
            m = fmaxf(m, __shfl_xor_sync(0xffffffffu, m, o));

        float e0 = __expf(s0 - m);
        float e1 = __expf(s1 - m);
        float e2 = __expf(s2 - m);
        float e3 = __expf(s3 - m);

        float sum = e0 + e1 + e2 + e3;
#pragma unroll
        for (int o = 16; o > 0; o >>= 1)
            sum += __shfl_xor_sync(0xffffffffu, sum, o);

        float rinv = 1.0f / sum;
        if (i < S) {
            float* row = attn + ((size_t)b * S + i) * S;
            if (v0) row[c0]     = e0 * rinv;
            if (v1) row[c0 + 1] = e1 * rinv;
            if (v2) row[c2]     = e2 * rinv;
            if (v3) row[c2 + 1] = e3 * rinv;
        }
    }
}

// ---------------------------------------------------------------------------
// Kernel B (Round-11 version, ncu ~29.5us): CLASS-ALIGNED, PHASE-SPLIT.
// Phase 1: class sum C (10 j), spilled to smem. Phase 2: F over all j.
// Phase 3: epilogue. 4 blocks/SM (64 regs).
// ---------------------------------------------------------------------------
__global__ __launch_bounds__(256, 4) void out_kernel(
    const float* __restrict__ attn, const float* __restrict__ v,
    const float* __restrict__ aw,
    float* __restrict__ out, int S)
{
    __shared__ float AsT[102][12];   // [j][ii], 48B rows (16B aligned)
    __shared__ ull   Cs0[5][256];    // C at h   (row-pair packed)
    __shared__ ull   Cs1[5][256];    // C at h+1

    const int b   = blockIdx.x;
    const int i0  = blockIdx.y * KV;
    const int t   = threadIdx.x;     // 0..255
    const int h   = 2 * t;
    const int NKq = S - 1;
    const int nrows = (S - i0 < KV) ? (S - i0) : KV;
    const bool is_class = (i0 < NKq);

    const float* vb = v + (size_t)b * S * HID;

    // Stage attn tile transposed: AsT[j][ii] = attn[i0+ii][j]
    for (int idx = t; idx < 102 * 12; idx += 256) {
        int jj = idx / 12;
        int ii = idx - jj * 12;
        float a = 0.f;
        if (ii < nrows && jj < S)
            a = attn[((size_t)b * S + i0 + ii) * S + jj];
        AsT[jj][ii] = a;
    }
    __syncthreads();

    // ---- Phase 1: class sum C over [i0, i0+KV), spill to smem ----
    if (is_class) {
        ull C0[5], C1[5];
#pragma unroll
        for (int r = 0; r < 5; ++r) { C0[r] = 0ull; C1[r] = 0ull; }

        auto bodyC = [&](int jj, float2 vc) {
            ull vlo = pack2(vc.x, vc.x);
            ull vhi = pack2(vc.y, vc.y);
            ulonglong2 a01 = *(const ulonglong2*)&AsT[jj][0];
            ulonglong2 a23 = *(const ulonglong2*)&AsT[jj][4];
            ull        a4  = *(const ull*)&AsT[jj][8];
            C0[0] = fma2(vlo, a01.x, C0[0]);  C1[0] = fma2(vhi, a01.x, C1[0]);
            C0[1] = fma2(vlo, a01.y, C0[1]);  C1[1] = fma2(vhi, a01.y, C1[1]);
            C0[2] = fma2(vlo, a23.x, C0[2]);  C1[2] = fma2(vhi, a23.x, C1[2]);
            C0[3] = fma2(vlo, a23.y, C0[3]);  C1[3] = fma2(vhi, a23.y, C1[3]);
            C0[4] = fma2(vlo, a4,    C0[4]);  C1[4] = fma2(vhi, a4,    C1[4]);
        };

        float2 u0 = *(const float2*)(vb + (size_t)(i0 + 0) * HID + h);
        float2 u1 = *(const float2*)(vb + (size_t)(i0 + 1) * HID + h);
        float2 u2 = *(const float2*)(vb + (size_t)(i0 + 2) * HID + h);
        float2 u3 = *(const float2*)(vb + (size_t)(i0 + 3) * HID + h);
        float2 u4 = *(const float2*)(vb + (size_t)(i0 + 4) * HID + h);
        bodyC(i0 + 0, u0);
        bodyC(i0 + 1, u1);
        bodyC(i0 + 2, u2);
        bodyC(i0 + 3, u3);
        bodyC(i0 + 4, u4);
        u0 = *(const float2*)(vb + (size_t)(i0 + 5) * HID + h);
        u1 = *(const float2*)(vb + (size_t)(i0 + 6) * HID + h);
        u2 = *(const float2*)(vb + (size_t)(i0 + 7) * HID + h);
        u3 = *(const float2*)(vb + (size_t)(i0 + 8) * HID + h);
        u4 = *(const float2*)(vb + (size_t)(i0 + 9) * HID + h);
        bodyC(i0 + 5, u0);
        bodyC(i0 + 6, u1);
        bodyC(i0 + 7, u2);
        bodyC(i0 + 8, u3);
        bodyC(i0 + 9, u4);

#pragma unroll
        for (int r = 0; r < 5; ++r) { Cs0[r][t] = C0[r]; Cs1[r][t] = C1[r]; }
    }

    // ---- Phase 2: F over all j ----
    ull F0[5], F1[5];
#pragma unroll
    for (int r = 0; r < 5; ++r) { F0[r] = 0ull; F1[r] = 0ull; }

    auto body = [&](int j, float2 vc) {
        ull vlo = pack2(vc.x, vc.x);
        ull vhi = pack2(vc.y, vc.y);
        ulonglong2 a01 = *(const ulonglong2*)&AsT[j][0];
        ulonglong2 a23 = *(const ulonglong2*)&AsT[j][4];
        ull        a4  = *(const ull*)&AsT[j][8];
        F0[0] = fma2(vlo, a01.x, F0[0]);  F1[0] = fma2(vhi, a01.x, F1[0]);
        F0[1] = fma2(vlo, a01.y, F0[1]);  F1[1] = fma2(vhi, a01.y, F1[1]);
        F0[2] = fma2(vlo, a23.x, F0[2]);  F1[2] = fma2(vhi, a23.x, F1[2]);
        F0[3] = fma2(vlo, a23.y, F0[3]);  F1[3] = fma2(vhi, a23.y, F1[3]);
        F0[4] = fma2(vlo, a4,    F0[4]);  F1[4] = fma2(vhi, a4,    F1[4]);
    };

    const float2 fz = make_float2(0.f, 0.f);

    float2 p0 = *(const float2*)(vb + 0 * (size_t)HID + h);
    float2 p1 = (1 < S) ? *(const float2*)(vb + 1 * (size_t)HID + h) : fz;
    float2 p2 = (2 < S) ? *(const float2*)(vb + 2 * (size_t)HID + h) : fz;
    float2 p3 = (3 < S) ? *(const float2*)(vb + 3 * (size_t)HID + h) : fz;

    int j = 0;
    // main loop: refill loads unconditional (j+7 < S guaranteed)
#pragma unroll 1
    for (; j + 7 < S; j += 4) {
        float2 n0 = *(const float2*)(vb + (size_t)(j + 4) * HID + h);
        float2 n1 = *(const float2*)(vb + (size_t)(j + 5) * HID + h);
        float2 n2 = *(const float2*)(vb + (size_t)(j + 6) * HID + h);
        float2 n3 = *(const float2*)(vb + (size_t)(j + 7) * HID + h);
        body(j + 0, p0);
        body(j + 1, p1);
        body(j + 2, p2);
        body(j + 3, p3);
        p0 = n0; p1 = n1; p2 = n2; p3 = n3;
    }
    // tail: ring holds V[j..j+3]; at most 7 j remain
    if (j < S)     body(j,     p0);
    if (j + 1 < S) body(j + 1, p1);
    if (j + 2 < S) body(j + 2, p2);
    if (j + 3 < S) body(j + 3, p3);
#pragma unroll 1
    for (int jj = j + 4; jj < S; ++jj) {
        float2 u = *(const float2*)(vb + (size_t)jj * HID + h);
        body(jj, u);
    }

    const float2 vq = *(const float2*)(vb + (size_t)NKq * HID + h);

    if (!is_class) {
        // ---- query tile: single row NKq at local ii = 0 ----
        const float2 w4 = *(const float2*)(aw + 4 * HID + h);
        const float2 w5 = *(const float2*)(aw + 5 * HID + h);
        float Fx = unpack2(F0[0]).x;
        float Fy = unpack2(F1[0]).x;
        float aqq = AsT[NKq][0];
        float2 o;
        o.x = w4.x * Fx + (w5.x - w4.x) * aqq * vq.x;
        o.y = w4.y * Fy + (w5.y - w4.y) * aqq * vq.y;
        *(float2*)(out + ((size_t)b * S + NKq) * HID + h) = o;
        return;
    }

    // ---- Phase 3: epilogue ----
    const float2 w0 = *(const float2*)(aw + 0 * HID + h);
    const float2 w1 = *(const float2*)(aw + 1 * HID + h);
    const float2 w2 = *(const float2*)(aw + 2 * HID + h);
    const float2 w3 = *(const float2*)(aw + 3 * HID + h);

    const float2 d12 = make_float2(w1.x - w2.x, w1.y - w2.y);
    const float2 d01 = make_float2(w0.x - w1.x, w0.y - w1.y);
    const float2 d32 = make_float2(w3.x - w2.x, w3.y - w2.y);

#pragma unroll
    for (int r = 0; r < 5; ++r) {
        float2 f0 = unpack2(F0[r]);       // F[2r][h], F[2r+1][h]
        float2 f1 = unpack2(F1[r]);       // F[2r][h+1], F[2r+1][h+1]
        float2 c0 = unpack2(Cs0[r][t]);
        float2 c1 = unpack2(Cs1[r][t]);

#pragma unroll
        for (int s = 0; s < 2; ++s) {
            int kk = 2 * r + s;
            int i = i0 + kk;
            float Fx = s ? f0.y : f0.x;
            float Fy = s ? f1.y : f1.x;
            float Cx = s ? c0.y : c0.x;
            float Cy = s ? c1.y : c1.x;
            float aii = AsT[i][kk];
            float aiq = AsT[NKq][kk];
            float2 vi = *(const float2*)(vb + (size_t)i * HID + h);  // L1-hot
            float2 o;
            o.x = w2.x * Fx + d12.x * Cx + d01.x * aii * vi.x + d32.x * aiq * vq.x;
            o.y = w2.y * Fy + d12.y * Cy + d01.y * aii * vi.y + d32.y * aiq * vq.y;
            *(float2*)(out + ((size_t)b * S + i) * HID + h) = o;
        }
    }
}

// ---------------------------------------------------------------------------
extern "C" void kernel_launch(void* const* d_in, const int* in_sizes, int n_in,
                              void* d_out, int out_size)
{
    const float* q  = (const float*)d_in[0];
    const float* k  = (const float*)d_in[1];
    const float* v  = (const float*)d_in[2];
    const float* aw = (const float*)d_in[3];

    long rows = (long)in_sizes[0] / HID;   // B * S
    int B = 64;
    int S = (int)(rows / B);
    if (S <= 0 || (long)B * S != rows) { B = 1; S = (int)rows; }

    float* out = (float*)d_out;
    long need_with_attn = (long)B * S * HID + (long)B * S * S;
    float* attn;
    if ((long)out_size >= need_with_attn) {
        attn = out + (long)B * S * HID;
    } else {
        void* p = nullptr;
        cudaGetSymbolAddress(&p, g_attn_scratch);
        attn = (float*)p;
    }

    dim3 gA(B, (S + TI_A - 1) / TI_A);
    qk_softmax_kernel<<<gA, 64>>>(q, k, attn, S);

    dim3 gB(B, (S + KV - 1) / KV);
    out_kernel<<<gB, 256>>>(attn, v, aw, out, S);
}

// round 15
// speedup vs baseline: 1.2919x; 1.2919x over previous
#include <cuda_runtime.h>
#include <math.h>
#include <stdint.h>

#define HID 512
#define TI_A 32
#define KV   10   // class size (N=K=10 problem family; S = N*K+1)

typedef unsigned long long ull;

__device__ __forceinline__ ull fma2(ull a, ull b, ull c) {
    ull d;
    asm("fma.rn.f32x2 %0, %1, %2, %3;" : "=l"(d) : "l"(a), "l"(b), "l"(c));
    return d;
}
__device__ __forceinline__ ull pack2(float lo, float hi) {
    ull d;
    asm("mov.b64 %0, {%1, %2};" : "=l"(d) : "f"(lo), "f"(hi));
    return d;
}
__device__ __forceinline__ float2 unpack2(ull a) {
    float lo, hi;
    asm("mov.b64 {%0, %1}, %2;" : "=f"(lo), "=f"(hi) : "l"(a));
    return make_float2(lo, hi);
}

// Fallback scratch for attn if d_out doesn't include the attn tensor.
__device__ float g_attn_scratch[64 * 128 * 128];

// ---------------------------------------------------------------------------
// Kernel A v5b: scores = Q K^T / sqrt(H), softmax, write attn.
// Block: (batch b, 32-row tile) -> grid (64, 4) = 256 blocks (~2/SM).
// 128 threads = 4 warps; warp ty owns rows iy8 = ty*8..+7, all 128 j.
// Thread micro-tile: 8 i x 4 j, j = {2tx, 2tx+1, 2tx+64, 2tx+65}.
// h in 16 chunks of 32 floats; register-staged double buffer with a
// SINGLE barrier per chunk (stores go to the other buffer):
//   load_regs(c+1) -> compute(cur) -> store_smem(cur^1) -> syncthreads.
// ---------------------------------------------------------------------------
__global__ __launch_bounds__(128) void qk_softmax_kernel(
    const float* __restrict__ q, const float* __restrict__ k,
    float* __restrict__ attn, int S)
{
    __shared__ ull Qs2[2][16][34];    // [buf][h2][i]
    __shared__ ull Ks2[2][16][130];   // [buf][h2][j]

    const int b   = blockIdx.x;
    const int i0  = blockIdx.y * TI_A;
    const int tid = threadIdx.x;      // 0..127
    const int tx  = tid & 31;
    const int ty  = tid >> 5;         // 0..3
    const int iy8 = ty * 8;
    const int h2l  = tid & 15;        // h-pair lane for loads (0..15)
    const int rsel = tid >> 4;        // row selector for loads (0..7)

    const float* qb = q + (size_t)b * S * HID;
    const float* kb = k + (size_t)b * S * HID;

    ull acc2[8][4];
#pragma unroll
    for (int a = 0; a < 8; ++a)
#pragma unroll
        for (int c = 0; c < 4; ++c) acc2[a][c] = 0ull;

    float2 qreg[4], kreg[16];

    auto load_regs = [&](int c) {
        int h0 = c * 32;
#pragma unroll
        for (int r = 0; r < 4; ++r) {
            int i = i0 + rsel + 8 * r;
            qreg[r] = (i < S) ? *(const float2*)(qb + (size_t)i * HID + h0 + h2l * 2)
                              : make_float2(0.f, 0.f);
        }
#pragma unroll
        for (int r = 0; r < 16; ++r) {
            int j = rsel + 8 * r;
            kreg[r] = (j < S) ? *(const float2*)(kb + (size_t)j * HID + h0 + h2l * 2)
                              : make_float2(0.f, 0.f);
        }
    };
    auto store_smem = [&](int buf) {
#pragma unroll
        for (int r = 0; r < 4; ++r)
            *(float2*)&Qs2[buf][h2l][rsel + 8 * r] = qreg[r];
#pragma unroll
        for (int r = 0; r < 16; ++r)
            *(float2*)&Ks2[buf][h2l][rsel + 8 * r] = kreg[r];
    };

    load_regs(0);
    store_smem(0);
    __syncthreads();

#pragma unroll 1
    for (int c = 0; c < 16; ++c) {
        int cur = c & 1;
        if (c + 1 < 16) load_regs(c + 1);   // LDGs fly over this chunk's compute

#pragma unroll
        for (int h2 = 0; h2 < 16; ++h2) {
            ulonglong2 q01 = *(const ulonglong2*)&Qs2[cur][h2][iy8];
            ulonglong2 q23 = *(const ulonglong2*)&Qs2[cur][h2][iy8 + 2];
            ulonglong2 q45 = *(const ulonglong2*)&Qs2[cur][h2][iy8 + 4];
            ulonglong2 q67 = *(const ulonglong2*)&Qs2[cur][h2][iy8 + 6];
            ulonglong2 ka  = *(const ulonglong2*)&Ks2[cur][h2][2 * tx];
            ulonglong2 kc  = *(const ulonglong2*)&Ks2[cur][h2][2 * tx + 64];
            acc2[0][0] = fma2(q01.x, ka.x, acc2[0][0]);
            acc2[0][1] = fma2(q01.x, ka.y, acc2[0][1]);
            acc2[0][2] = fma2(q01.x, kc.x, acc2[0][2]);
            acc2[0][3] = fma2(q01.x, kc.y, acc2[0][3]);
            acc2[1][0] = fma2(q01.y, ka.x, acc2[1][0]);
            acc2[1][1] = fma2(q01.y, ka.y, acc2[1][1]);
            acc2[1][2] = fma2(q01.y, kc.x, acc2[1][2]);
            acc2[1][3] = fma2(q01.y, kc.y, acc2[1][3]);
            acc2[2][0] = fma2(q23.x, ka.x, acc2[2][0]);
            acc2[2][1] = fma2(q23.x, ka.y, acc2[2][1]);
            acc2[2][2] = fma2(q23.x, kc.x, acc2[2][2]);
            acc2[2][3] = fma2(q23.x, kc.y, acc2[2][3]);
            acc2[3][0] = fma2(q23.y, ka.x, acc2[3][0]);
            acc2[3][1] = fma2(q23.y, ka.y, acc2[3][1]);
            acc2[3][2] = fma2(q23.y, kc.x, acc2[3][2]);
            acc2[3][3] = fma2(q23.y, kc.y, acc2[3][3]);
            acc2[4][0] = fma2(q45.x, ka.x, acc2[4][0]);
            acc2[4][1] = fma2(q45.x, ka.y, acc2[4][1]);
            acc2[4][2] = fma2(q45.x, kc.x, acc2[4][2]);
            acc2[4][3] = fma2(q45.x, kc.y, acc2[4][3]);
            acc2[5][0] = fma2(q45.y, ka.x, acc2[5][0]);
            acc2[5][1] = fma2(q45.y, ka.y, acc2[5][1]);
            acc2[5][2] = fma2(q45.y, kc.x, acc2[5][2]);
            acc2[5][3] = fma2(q45.y, kc.y, acc2[5][3]);
            acc2[6][0] = fma2(q67.x, ka.x, acc2[6][0]);
            acc2[6][1] = fma2(q67.x, ka.y, acc2[6][1]);
            acc2[6][2] = fma2(q67.x, kc.x, acc2[6][2]);
            acc2[6][3] = fma2(q67.x, kc.y, acc2[6][3]);
            acc2[7][0] = fma2(q67.y, ka.x, acc2[7][0]);
            acc2[7][1] = fma2(q67.y, ka.y, acc2[7][1]);
            acc2[7][2] = fma2(q67.y, kc.x, acc2[7][2]);
            acc2[7][3] = fma2(q67.y, kc.y, acc2[7][3]);
        }
        if (c + 1 < 16) store_smem(cur ^ 1);   // other buffer: no race with readers of `cur`
        __syncthreads();                        // single barrier per chunk
    }

    const float inv_t = 0.04419417382415922f;  // 1/sqrt(512)

    const int c0 = 2 * tx;
    const int c2 = 2 * tx + 64;
    const bool v0 = (c0    ) < S;
    const bool v1 = (c0 + 1) < S;
    const bool v2 = (c2    ) < S;
    const bool v3 = (c2 + 1) < S;

#pragma unroll
    for (int si = 0; si < 8; ++si) {
        int i = i0 + iy8 + si;
        float2 a0 = unpack2(acc2[si][0]);
        float2 a1 = unpack2(acc2[si][1]);
        float2 a2 = unpack2(acc2[si][2]);
        float2 a3 = unpack2(acc2[si][3]);
        float s0 = v0 ? (a0.x + a0.y) * inv_t : -INFINITY;
        float s1 = v1 ? (a1.x + a1.y) * inv_t : -INFINITY;
        float s2 = v2 ? (a2.x + a2.y) * inv_t : -INFINITY;
        float s3 = v3 ? (a3.x + a3.y) * inv_t : -INFINITY;

        float m = fmaxf(fmaxf(s0, s1), fmaxf(s2, s3));
#pragma unroll
        for (int o = 16; o > 0; o >>= 1)
            m = fmaxf(m, __shfl_xor_sync(0xffffffffu, m, o));

        float e0 = __expf(s0 - m);
        float e1 = __expf(s1 - m);
        float e2 = __expf(s2 - m);
        float e3 = __expf(s3 - m);

        float sum = e0 + e1 + e2 + e3;
#pragma unroll
        for (int o = 16; o > 0; o >>= 1)
            sum += __shfl_xor_sync(0xffffffffu, sum, o);

        float rinv = 1.0f / sum;
        if (i < S) {
            float* row = attn + ((size_t)b * S + i) * S;
            if (v0) row[c0]     = e0 * rinv;
            if (v1) row[c0 + 1] = e1 * rinv;
            if (v2) row[c2]     = e2 * rinv;
            if (v3) row[c2 + 1] = e3 * rinv;
        }
    }
}

// ---------------------------------------------------------------------------
// Kernel B (Round-11 version, ncu ~29.5us, FROZEN): CLASS-ALIGNED, PHASE-SPLIT.
// Phase 1: class sum C (10 j), spilled to smem. Phase 2: F over all j.
// Phase 3: epilogue. 4 blocks/SM (64 regs).
// ---------------------------------------------------------------------------
__global__ __launch_bounds__(256, 4) void out_kernel(
    const float* __restrict__ attn, const float* __restrict__ v,
    const float* __restrict__ aw,
    float* __restrict__ out, int S)
{
    __shared__ float AsT[102][12];   // [j][ii], 48B rows (16B aligned)
    __shared__ ull   Cs0[5][256];    // C at h   (row-pair packed)
    __shared__ ull   Cs1[5][256];    // C at h+1

    const int b   = blockIdx.x;
    const int i0  = blockIdx.y * KV;
    const int t   = threadIdx.x;     // 0..255
    const int h   = 2 * t;
    const int NKq = S - 1;
    const int nrows = (S - i0 < KV) ? (S - i0) : KV;
    const bool is_class = (i0 < NKq);

    const float* vb = v + (size_t)b * S * HID;

    // Stage attn tile transposed: AsT[j][ii] = attn[i0+ii][j]
    for (int idx = t; idx < 102 * 12; idx += 256) {
        int jj = idx / 12;
        int ii = idx - jj * 12;
        float a = 0.f;
        if (ii < nrows && jj < S)
            a = attn[((size_t)b * S + i0 + ii) * S + jj];
        AsT[jj][ii] = a;
    }
    __syncthreads();

    // ---- Phase 1: class sum C over [i0, i0+KV), spill to smem ----
    if (is_class) {
        ull C0[5], C1[5];
#pragma unroll
        for (int r = 0; r < 5; ++r) { C0[r] = 0ull; C1[r] = 0ull; }

        auto bodyC = [&](int jj, float2 vc) {
            ull vlo = pack2(vc.x, vc.x);
            ull vhi = pack2(vc.y, vc.y);
            ulonglong2 a01 = *(const ulonglong2*)&AsT[jj][0];
            ulonglong2 a23 = *(const ulonglong2*)&AsT[jj][4];
            ull        a4  = *(const ull*)&AsT[jj][8];
            C0[0] = fma2(vlo, a01.x, C0[0]);  C1[0] = fma2(vhi, a01.x, C1[0]);
            C0[1] = fma2(vlo, a01.y, C0[1]);  C1[1] = fma2(vhi, a01.y, C1[1]);
            C0[2] = fma2(vlo, a23.x, C0[2]);  C1[2] = fma2(vhi, a23.x, C1[2]);
            C0[3] = fma2(vlo, a23.y, C0[3]);  C1[3] = fma2(vhi, a23.y, C1[3]);
            C0[4] = fma2(vlo, a4,    C0[4]);  C1[4] = fma2(vhi, a4,    C1[4]);
        };

        float2 u0 = *(const float2*)(vb + (size_t)(i0 + 0) * HID + h);
        float2 u1 = *(const float2*)(vb + (size_t)(i0 + 1) * HID + h);
        float2 u2 = *(const float2*)(vb + (size_t)(i0 + 2) * HID + h);
        float2 u3 = *(const float2*)(vb + (size_t)(i0 + 3) * HID + h);
        float2 u4 = *(const float2*)(vb + (size_t)(i0 + 4) * HID + h);
        bodyC(i0 + 0, u0);
        bodyC(i0 + 1, u1);
        bodyC(i0 + 2, u2);
        bodyC(i0 + 3, u3);
        bodyC(i0 + 4, u4);
        u0 = *(const float2*)(vb + (size_t)(i0 + 5) * HID + h);
        u1 = *(const float2*)(vb + (size_t)(i0 + 6) * HID + h);
        u2 = *(const float2*)(vb + (size_t)(i0 + 7) * HID + h);
        u3 = *(const float2*)(vb + (size_t)(i0 + 8) * HID + h);
        u4 = *(const float2*)(vb + (size_t)(i0 + 9) * HID + h);
        bodyC(i0 + 5, u0);
        bodyC(i0 + 6, u1);
        bodyC(i0 + 7, u2);
        bodyC(i0 + 8, u3);
        bodyC(i0 + 9, u4);

#pragma unroll
        for (int r = 0; r < 5; ++r) { Cs0[r][t] = C0[r]; Cs1[r][t] = C1[r]; }
    }

    // ---- Phase 2: F over all j ----
    ull F0[5], F1[5];
#pragma unroll
    for (int r = 0; r < 5; ++r) { F0[r] = 0ull; F1[r] = 0ull; }

    auto body = [&](int j, float2 vc) {
        ull vlo = pack2(vc.x, vc.x);
        ull vhi = pack2(vc.y, vc.y);
        ulonglong2 a01 = *(const ulonglong2*)&AsT[j][0];
        ulonglong2 a23 = *(const ulonglong2*)&AsT[j][4];
        ull        a4  = *(const ull*)&AsT[j][8];
        F0[0] = fma2(vlo, a01.x, F0[0]);  F1[0] = fma2(vhi, a01.x, F1[0]);
        F0[1] = fma2(vlo, a01.y, F0[1]);  F1[1] = fma2(vhi, a01.y, F1[1]);
        F0[2] = fma2(vlo, a23.x, F0[2]);  F1[2] = fma2(vhi, a23.x, F1[2]);
        F0[3] = fma2(vlo, a23.y, F0[3]);  F1[3] = fma2(vhi, a23.y, F1[3]);
        F0[4] = fma2(vlo, a4,    F0[4]);  F1[4] = fma2(vhi, a4,    F1[4]);
    };

    const float2 fz = make_float2(0.f, 0.f);

    float2 p0 = *(const float2*)(vb + 0 * (size_t)HID + h);
    float2 p1 = (1 < S) ? *(const float2*)(vb + 1 * (size_t)HID + h) : fz;
    float2 p2 = (2 < S) ? *(const float2*)(vb + 2 * (size_t)HID + h) : fz;
    float2 p3 = (3 < S) ? *(const float2*)(vb + 3 * (size_t)HID + h) : fz;

    int j = 0;
    // main loop: refill loads unconditional (j+7 < S guaranteed)
#pragma unroll 1
    for (; j + 7 < S; j += 4) {
        float2 n0 = *(const float2*)(vb + (size_t)(j + 4) * HID + h);
        float2 n1 = *(const float2*)(vb + (size_t)(j + 5) * HID + h);
        float2 n2 = *(const float2*)(vb + (size_t)(j + 6) * HID + h);
        float2 n3 = *(const float2*)(vb + (size_t)(j + 7) * HID + h);
        body(j + 0, p0);
        body(j + 1, p1);
        body(j + 2, p2);
        body(j + 3, p3);
        p0 = n0; p1 = n1; p2 = n2; p3 = n3;
    }
    // tail: ring holds V[j..j+3]; at most 7 j remain
    if (j < S)     body(j,     p0);
    if (j + 1 < S) body(j + 1, p1);
    if (j + 2 < S) body(j + 2, p2);
    if (j + 3 < S) body(j + 3, p3);
#pragma unroll 1
    for (int jj = j + 4; jj < S; ++jj) {
        float2 u = *(const float2*)(vb + (size_t)jj * HID + h);
        body(jj, u);
    }

    const float2 vq = *(const float2*)(vb + (size_t)NKq * HID + h);

    if (!is_class) {
        // ---- query tile: single row NKq at local ii = 0 ----
        const float2 w4 = *(const float2*)(aw + 4 * HID + h);
        const float2 w5 = *(const float2*)(aw + 5 * HID + h);
        float Fx = unpack2(F0[0]).x;
        float Fy = unpack2(F1[0]).x;
        float aqq = AsT[NKq][0];
        float2 o;
        o.x = w4.x * Fx + (w5.x - w4.x) * aqq * vq.x;
        o.y = w4.y * Fy + (w5.y - w4.y) * aqq * vq.y;
        *(float2*)(out + ((size_t)b * S + NKq) * HID + h) = o;
        return;
    }

    // ---- Phase 3: epilogue ----
    const float2 w0 = *(const float2*)(aw + 0 * HID + h);
    const float2 w1 = *(const float2*)(aw + 1 * HID + h);
    const float2 w2 = *(const float2*)(aw + 2 * HID + h);
    const float2 w3 = *(const float2*)(aw + 3 * HID + h);

    const float2 d12 = make_float2(w1.x - w2.x, w1.y - w2.y);
    const float2 d01 = make_float2(w0.x - w1.x, w0.y - w1.y);
    const float2 d32 = make_float2(w3.x - w2.x, w3.y - w2.y);

#pragma unroll
    for (int r = 0; r < 5; ++r) {
        float2 f0 = unpack2(F0[r]);       // F[2r][h], F[2r+1][h]
        float2 f1 = unpack2(F1[r]);       // F[2r][h+1], F[2r+1][h+1]
        float2 c0 = unpack2(Cs0[r][t]);
        float2 c1 = unpack2(Cs1[r][t]);

#pragma unroll
        for (int s = 0; s < 2; ++s) {
            int kk = 2 * r + s;
            int i = i0 + kk;
            float Fx = s ? f0.y : f0.x;
            float Fy = s ? f1.y : f1.x;
            float Cx = s ? c0.y : c0.x;
            float Cy = s ? c1.y : c1.x;
            float aii = AsT[i][kk];
            float aiq = AsT[NKq][kk];
            float2 vi = *(const float2*)(vb + (size_t)i * HID + h);  // L1-hot
            float2 o;
            o.x = w2.x * Fx + d12.x * Cx + d01.x * aii * vi.x + d32.x * aiq * vq.x;
            o.y = w2.y * Fy + d12.y * Cy + d01.y * aii * vi.y + d32.y * aiq * vq.y;
            *(float2*)(out + ((size_t)b * S + i) * HID + h) = o;
        }
    }
}

// ---------------------------------------------------------------------------
extern "C" void kernel_launch(void* const* d_in, const int* in_sizes, int n_in,
                              void* d_out, int out_size)
{
    const float* q  = (const float*)d_in[0];
    const float* k  = (const float*)d_in[1];
    const float* v  = (const float*)d_in[2];
    const float* aw = (const float*)d_in[3];

    long rows = (long)in_sizes[0] / HID;   // B * S
    int B = 64;
    int S = (int)(rows / B);
    if (S <= 0 || (long)B * S != rows) { B = 1; S = (int)rows; }

    float* out = (float*)d_out;
    long need_with_attn = (long)B * S * HID + (long)B * S * S;
    float* attn;
    if ((long)out_size >= need_with_attn) {
        attn = out + (long)B * S * HID;
    } else {
        void* p = nullptr;
        cudaGetSymbolAddress(&p, g_attn_scratch);
        attn = (float*)p;
    }

    dim3 gA(B, (S + TI_A - 1) / TI_A);
    qk_softmax_kernel<<<gA, 128>>>(q, k, attn, S);

    dim3 gB(B, (S + KV - 1) / KV);
    out_kernel<<<gB, 256>>>(attn, v, aw, out, S);
}